// round 2
// baseline (speedup 1.0000x reference)
#include <cuda_runtime.h>

// Chamfer distance, pc1/pc2: (1, 16384, 3) fp32 -> scalar fp32.
// Strategy: two directional NN-min passes fused into one kernel (blockIdx.z),
// inner loop uses packed fma.rn.f32x2. Per-query x^2 folded out of the min.

#define P_PTS 16384
#define BLOCK 256
#define RQ 8                       // query points per thread
#define QPB (BLOCK * RQ)           // 2048 queries per block
#define QTILES (P_PTS / QPB)       // 8
#define YCHUNKS 16
#define YCHUNK (P_PTS / YCHUNKS)   // 1024 reference points per block
#define REDB 16                    // reduce-stage-1 blocks per direction

// Scratch (no allocations allowed): per-query running min keys + partial sums.
__device__ unsigned int g_min[2][P_PTS];
__device__ float g_part[2 * REDB];

#define FMA2(out, a, b, c) \
    asm("fma.rn.f32x2 %0, %1, %2, %3;" : "=l"(out) : "l"(a), "l"(b), "l"(c))
#define PACK2(out, lo, hi) \
    asm("mov.b64 %0, {%1, %2};" : "=l"(out) : "f"(lo), "f"(hi))
#define UNPACK2(lo, hi, in) \
    asm("mov.b64 {%0, %1}, %2;" : "=f"(lo), "=f"(hi) : "l"(in))

// Monotone float -> uint mapping (total order preserved), so atomicMin on uint
// implements exact float min. Deterministic (min is associative/commutative).
__device__ __forceinline__ unsigned int f2key(float f) {
    unsigned int b = __float_as_uint(f);
    unsigned int mask = ((unsigned int)((int)b >> 31)) | 0x80000000u;
    return b ^ mask;
}
__device__ __forceinline__ float key2f(unsigned int k) {
    unsigned int b = (k & 0x80000000u) ? (k ^ 0x80000000u) : ~k;
    return __uint_as_float(b);
}

__global__ void init_kernel() {
    int i = blockIdx.x * blockDim.x + threadIdx.x;
    ((unsigned int*)g_min)[i] = 0xFFFFFFFFu;   // covers 2*P_PTS exactly
}

__global__ void __launch_bounds__(BLOCK) pass_kernel(
    const float* __restrict__ pc1, const float* __restrict__ pc2)
{
    const float* Q;
    const float* Y;
    unsigned int* gm;
    if (blockIdx.z == 0) { Q = pc1; Y = pc2; gm = g_min[0]; }
    else                 { Q = pc2; Y = pc1; gm = g_min[1]; }

    // Reference tile, stored duplicated so LDS.128 yields packed-broadcast pairs:
    // per point: [-2y0,-2y0, -2y1,-2y1, -2y2,-2y2, y2sum,y2sum]
    __shared__ float sh[YCHUNK * 8];

    const int ybase = blockIdx.y * YCHUNK;
    for (int i = threadIdx.x; i < YCHUNK; i += BLOCK) {
        float y0 = Y[3 * (ybase + i) + 0];
        float y1 = Y[3 * (ybase + i) + 1];
        float y2 = Y[3 * (ybase + i) + 2];
        float yy = y0 * y0 + y1 * y1 + y2 * y2;
        float* s = &sh[i * 8];
        s[0] = -2.0f * y0; s[1] = -2.0f * y0;
        s[2] = -2.0f * y1; s[3] = -2.0f * y1;
        s[4] = -2.0f * y2; s[5] = -2.0f * y2;
        s[6] = yy;         s[7] = yy;
    }
    __syncthreads();

    const int q0 = blockIdx.x * QPB + threadIdx.x;

    // 8 query points packed as 4 f32x2 pairs per coordinate.
    unsigned long long Qx[4], Qy[4], Qz[4];
    float m[8];
#pragma unroll
    for (int k = 0; k < 4; k++) {
        int qa = q0 + (2 * k + 0) * BLOCK;
        int qb = q0 + (2 * k + 1) * BLOCK;
        PACK2(Qx[k], Q[3 * qa + 0], Q[3 * qb + 0]);
        PACK2(Qy[k], Q[3 * qa + 1], Q[3 * qb + 1]);
        PACK2(Qz[k], Q[3 * qa + 2], Q[3 * qb + 2]);
        m[2 * k + 0] = __int_as_float(0x7F800000);  // +inf
        m[2 * k + 1] = __int_as_float(0x7F800000);
    }

#pragma unroll 4
    for (int j = 0; j < YCHUNK; j++) {
        const ulonglong2* sp = (const ulonglong2*)&sh[j * 8];
        ulonglong2 A = sp[0];   // A.x = (-2y0,-2y0), A.y = (-2y1,-2y1)
        ulonglong2 B = sp[1];   // B.x = (-2y2,-2y2), B.y = (yy, yy)
#pragma unroll
        for (int k = 0; k < 4; k++) {
            unsigned long long t;
            FMA2(t, Qx[k], A.x, B.y);   // yy - 2*x0*y0
            FMA2(t, Qy[k], A.y, t);
            FMA2(t, Qz[k], B.x, t);     // = yy - 2*(x.y)  (x^2 added later)
            float lo, hi;
            UNPACK2(lo, hi, t);
            m[2 * k + 0] = fminf(m[2 * k + 0], lo);
            m[2 * k + 1] = fminf(m[2 * k + 1], hi);
        }
    }

#pragma unroll
    for (int k = 0; k < 8; k++) {
        int q = q0 + k * BLOCK;
        atomicMin(&gm[q], f2key(m[k]));
    }
}

__global__ void __launch_bounds__(512) reduce1_kernel(
    const float* __restrict__ pc1, const float* __restrict__ pc2)
{
    const int dir = blockIdx.y;
    const float* X = (dir == 0) ? pc1 : pc2;
    const unsigned int* gm = g_min[dir];

    float s = 0.0f;
#pragma unroll
    for (int half = 0; half < 2; half++) {
        int e = blockIdx.x * 512 + threadIdx.x + half * (REDB * 512);
        float v = key2f(gm[e]);
        float x0 = X[3 * e + 0], x1 = X[3 * e + 1], x2 = X[3 * e + 2];
        float d = v + (x0 * x0 + x1 * x1 + x2 * x2);  // full squared NN distance
        if (d < 2.0f) s += d;                          // threshold: >=2 -> 0
    }
#pragma unroll
    for (int o = 16; o; o >>= 1) s += __shfl_xor_sync(0xFFFFFFFFu, s, o);

    __shared__ float ws[16];
    if ((threadIdx.x & 31) == 0) ws[threadIdx.x >> 5] = s;
    __syncthreads();
    if (threadIdx.x < 16) {
        float t = ws[threadIdx.x];
#pragma unroll
        for (int o = 8; o; o >>= 1) t += __shfl_xor_sync(0x0000FFFFu, t, o);
        if (threadIdx.x == 0)
            g_part[dir * REDB + blockIdx.x] = t * (1.0f / (float)P_PTS);
    }
}

__global__ void reduce2_kernel(float* __restrict__ out) {
    float t = g_part[threadIdx.x];  // 32 partials
#pragma unroll
    for (int o = 16; o; o >>= 1) t += __shfl_xor_sync(0xFFFFFFFFu, t, o);
    if (threadIdx.x == 0) out[0] = t;
}

extern "C" void kernel_launch(void* const* d_in, const int* in_sizes, int n_in,
                              void* d_out, int out_size)
{
    const float* pc1 = (const float*)d_in[0];
    const float* pc2 = (const float*)d_in[1];
    float* out = (float*)d_out;

    init_kernel<<<(2 * P_PTS) / 1024, 1024>>>();
    pass_kernel<<<dim3(QTILES, YCHUNKS, 2), BLOCK>>>(pc1, pc2);
    reduce1_kernel<<<dim3(REDB, 2), 512>>>(pc1, pc2);
    reduce2_kernel<<<1, 32>>>(out);
}

// round 3
// speedup vs baseline: 1.2789x; 1.2789x over previous
#include <cuda_runtime.h>

// Chamfer distance, pc1/pc2: (1, 16384, 3) fp32 -> scalar fp32.
// fma.rn.f32x2 inner loop; per-query x^2 folded out of the min.
// R3: RQ=16 for issue-slot headroom (fma-pipe-bound), fine y-tiles for balance.

#define P_PTS 16384
#define BLOCK 256
#define RQ 16                      // query points per thread (8 packed pairs)
#define QPB (BLOCK * RQ)           // 4096 queries per block
#define QTILES (P_PTS / QPB)       // 4
#define YCHUNKS 128
#define YCHUNK (P_PTS / YCHUNKS)   // 128 reference points per block
#define REDB 16                    // reduce-stage-1 blocks per direction

__device__ unsigned int g_min[2][P_PTS];
__device__ float g_part[2 * REDB];

#define FMA2(out, a, b, c) \
    asm("fma.rn.f32x2 %0, %1, %2, %3;" : "=l"(out) : "l"(a), "l"(b), "l"(c))
#define PACK2(out, lo, hi) \
    asm("mov.b64 %0, {%1, %2};" : "=l"(out) : "f"(lo), "f"(hi))
#define UNPACK2(lo, hi, in) \
    asm("mov.b64 {%0, %1}, %2;" : "=f"(lo), "=f"(hi) : "l"(in))

// Monotone float->uint key: atomicMin on uint == exact float min (deterministic).
__device__ __forceinline__ unsigned int f2key(float f) {
    unsigned int b = __float_as_uint(f);
    unsigned int mask = ((unsigned int)((int)b >> 31)) | 0x80000000u;
    return b ^ mask;
}
__device__ __forceinline__ float key2f(unsigned int k) {
    unsigned int b = (k & 0x80000000u) ? (k ^ 0x80000000u) : ~k;
    return __uint_as_float(b);
}

__global__ void init_kernel() {
    int i = blockIdx.x * blockDim.x + threadIdx.x;
    ((unsigned int*)g_min)[i] = 0xFFFFFFFFu;   // 2*P_PTS entries exactly
}

__global__ void __launch_bounds__(BLOCK, 2) pass_kernel(
    const float* __restrict__ pc1, const float* __restrict__ pc2)
{
    const float* Q;
    const float* Y;
    unsigned int* gm;
    if (blockIdx.z == 0) { Q = pc1; Y = pc2; gm = g_min[0]; }
    else                 { Q = pc2; Y = pc1; gm = g_min[1]; }

    // Reference tile, duplicated for packed-broadcast LDS.128:
    // per point: [-2y0,-2y0, -2y1,-2y1, -2y2,-2y2, yy,yy]
    __shared__ float sh[YCHUNK * 8];

    const int ybase = blockIdx.y * YCHUNK;
    if (threadIdx.x < YCHUNK) {
        int i = threadIdx.x;
        float y0 = Y[3 * (ybase + i) + 0];
        float y1 = Y[3 * (ybase + i) + 1];
        float y2 = Y[3 * (ybase + i) + 2];
        float yy = y0 * y0 + y1 * y1 + y2 * y2;
        float* s = &sh[i * 8];
        s[0] = -2.0f * y0; s[1] = -2.0f * y0;
        s[2] = -2.0f * y1; s[3] = -2.0f * y1;
        s[4] = -2.0f * y2; s[5] = -2.0f * y2;
        s[6] = yy;         s[7] = yy;
    }
    __syncthreads();

    const int q0 = blockIdx.x * QPB + threadIdx.x;

    // 16 query points as 8 packed f32x2 pairs per coordinate.
    unsigned long long Qx[8], Qy[8], Qz[8];
    float m[16];
#pragma unroll
    for (int k = 0; k < 8; k++) {
        int qa = q0 + (2 * k + 0) * BLOCK;
        int qb = q0 + (2 * k + 1) * BLOCK;
        PACK2(Qx[k], Q[3 * qa + 0], Q[3 * qb + 0]);
        PACK2(Qy[k], Q[3 * qa + 1], Q[3 * qb + 1]);
        PACK2(Qz[k], Q[3 * qa + 2], Q[3 * qb + 2]);
        m[2 * k + 0] = __int_as_float(0x7F800000);  // +inf
        m[2 * k + 1] = __int_as_float(0x7F800000);
    }

#pragma unroll 2
    for (int j = 0; j < YCHUNK; j++) {
        const ulonglong2* sp = (const ulonglong2*)&sh[j * 8];
        ulonglong2 A = sp[0];   // (-2y0,-2y0), (-2y1,-2y1)
        ulonglong2 B = sp[1];   // (-2y2,-2y2), (yy, yy)
#pragma unroll
        for (int k = 0; k < 8; k++) {
            unsigned long long t;
            FMA2(t, Qx[k], A.x, B.y);   // yy - 2*x0*y0
            FMA2(t, Qy[k], A.y, t);
            FMA2(t, Qz[k], B.x, t);     // = yy - 2*(x.y); x^2 added in reduce
            float lo, hi;
            UNPACK2(lo, hi, t);
            m[2 * k + 0] = fminf(m[2 * k + 0], lo);
            m[2 * k + 1] = fminf(m[2 * k + 1], hi);
        }
    }

#pragma unroll
    for (int k = 0; k < RQ; k++) {
        int q = q0 + k * BLOCK;
        atomicMin(&gm[q], f2key(m[k]));
    }
}

__global__ void __launch_bounds__(512) reduce1_kernel(
    const float* __restrict__ pc1, const float* __restrict__ pc2)
{
    const int dir = blockIdx.y;
    const float* X = (dir == 0) ? pc1 : pc2;
    const unsigned int* gm = g_min[dir];

    float s = 0.0f;
#pragma unroll
    for (int half = 0; half < 2; half++) {
        int e = blockIdx.x * 512 + threadIdx.x + half * (REDB * 512);
        float v = key2f(gm[e]);
        float x0 = X[3 * e + 0], x1 = X[3 * e + 1], x2 = X[3 * e + 2];
        float d = v + (x0 * x0 + x1 * x1 + x2 * x2);  // full squared NN distance
        if (d < 2.0f) s += d;                          // threshold: >=2 -> 0
    }
#pragma unroll
    for (int o = 16; o; o >>= 1) s += __shfl_xor_sync(0xFFFFFFFFu, s, o);

    __shared__ float ws[16];
    if ((threadIdx.x & 31) == 0) ws[threadIdx.x >> 5] = s;
    __syncthreads();
    if (threadIdx.x < 16) {
        float t = ws[threadIdx.x];
#pragma unroll
        for (int o = 8; o; o >>= 1) t += __shfl_xor_sync(0x0000FFFFu, t, o);
        if (threadIdx.x == 0)
            g_part[dir * REDB + blockIdx.x] = t * (1.0f / (float)P_PTS);
    }
}

__global__ void reduce2_kernel(float* __restrict__ out) {
    float t = g_part[threadIdx.x];  // 32 partials
#pragma unroll
    for (int o = 16; o; o >>= 1) t += __shfl_xor_sync(0xFFFFFFFFu, t, o);
    if (threadIdx.x == 0) out[0] = t;
}

extern "C" void kernel_launch(void* const* d_in, const int* in_sizes, int n_in,
                              void* d_out, int out_size)
{
    const float* pc1 = (const float*)d_in[0];
    const float* pc2 = (const float*)d_in[1];
    float* out = (float*)d_out;

    init_kernel<<<(2 * P_PTS) / 1024, 1024>>>();
    pass_kernel<<<dim3(QTILES, YCHUNKS, 2), BLOCK>>>(pc1, pc2);
    reduce1_kernel<<<dim3(REDB, 2), 512>>>(pc1, pc2);
    reduce2_kernel<<<1, 32>>>(out);
}